// round 13
// baseline (speedup 1.0000x reference)
#include <cuda_runtime.h>
#include <cuda_bf16.h>
#include <math.h>

// ---------------- problem constants ----------------
#define BATCH    2
#define LQ       8192
#define DM       256
#define DFFN     1024
#define NHEADS   8
#define NLEV     4
#define NPTS     4
#define STOT     21760           // 128*128 + 64*64 + 32*32 + 16*16
#define ROWS     (BATCH*LQ)      // 16384
#define MVAL     (BATCH*STOT)    // 43520
#define NOA      384             // fused off(256)+attn(128)

typedef unsigned short u16;

// ---------------- device scratch (allocation-free) ----------------
__device__ u16   g_q2  [ROWS * 512];        // (tgt+pos) hi|lo pairs
__device__ u16   g_src2[MVAL * 512];
__device__ float g_val [MVAL * DM];
__device__ float g_offa[ROWS * NOA];
__device__ u16   g_smp2[ROWS * 512];
__device__ float g_xpre[ROWS * DM];
__device__ float g_x   [ROWS * DM];
__device__ u16   g_x2  [ROWS * 512];
__device__ u16   g_h2  [ROWS * 2048];
__device__ float g_res [ROWS * DM];
__device__ u16   g_wv2  [768 * DM];          // [hi; hi; lo]
__device__ u16   g_wcat2[768 * NOA];
__device__ u16   g_wout2[768 * DM];
__device__ u16   g_w12  [768 * DFFN];
__device__ u16   g_w22  [3072 * DM];
__device__ float g_bcat [NOA];

// ---------------- hi/lo helpers ----------------
__device__ __forceinline__ void split1(float v, u16& h, u16& l) {
    __nv_bfloat16 hb = __float2bfloat16(v);
    __nv_bfloat16 lb = __float2bfloat16(v - __bfloat162float(hb));
    h = *(u16*)&hb; l = *(u16*)&lb;
}

// q2 = pair(tgt + qpos); rows x 512 (cols 0..255 hi, 256..511 lo)
__global__ void add_cvt_kernel(const float* __restrict__ a, const float* __restrict__ b,
                               u16* __restrict__ o) {
    int i = blockIdx.x * blockDim.x + threadIdx.x;       // ROWS*64
    if (i >= ROWS * 64) return;
    int row = i >> 6, c = (i & 63) * 4;
    float4 x = ((const float4*)(a + (size_t)row * 256))[c >> 2];
    float4 y = ((const float4*)(b + (size_t)row * 256))[c >> 2];
    x.x += y.x; x.y += y.y; x.z += y.z; x.w += y.w;
    u16 h[4], l[4];
    split1(x.x, h[0], l[0]); split1(x.y, h[1], l[1]);
    split1(x.z, h[2], l[2]); split1(x.w, h[3], l[3]);
    *(uint2*)(o + (size_t)row * 512 + c)       = *(uint2*)h;
    *(uint2*)(o + (size_t)row * 512 + 256 + c) = *(uint2*)l;
}

// pair-convert activations: (rows x 256) f32 -> (rows x 512) u16
__global__ void cvt_kernel(const float* __restrict__ a, u16* __restrict__ o, int rows) {
    int i = blockIdx.x * blockDim.x + threadIdx.x;
    if (i >= rows * 64) return;
    int row = i >> 6, c = (i & 63) * 4;
    float4 x = ((const float4*)(a + (size_t)row * 256))[c >> 2];
    u16 h[4], l[4];
    split1(x.x, h[0], l[0]); split1(x.y, h[1], l[1]);
    split1(x.z, h[2], l[2]); split1(x.w, h[3], l[3]);
    *(uint2*)(o + (size_t)row * 512 + c)       = *(uint2*)h;
    *(uint2*)(o + (size_t)row * 512 + 256 + c) = *(uint2*)l;
}

// weight convert: (K x N) f32 -> (3K x N) u16: rows [0,K)=hi, [K,2K)=hi, [2K,3K)=lo
__global__ void wcvt_kernel(const float* __restrict__ w, u16* __restrict__ o, int K, int N) {
    int i = blockIdx.x * blockDim.x + threadIdx.x;
    if (i >= K * N) return;
    int k = i / N, n = i % N;
    u16 h, l; split1(w[i], h, l);
    o[(size_t)k * N + n] = h;
    o[(size_t)(K + k) * N + n] = h;
    o[(size_t)(2 * K + k) * N + n] = l;
}

// concat Woff|Wat -> 3-block (768 x 384) + bias concat
__global__ void concat_cvt_kernel(const float* __restrict__ Woff, const float* __restrict__ Wat,
                                  const float* __restrict__ boff, const float* __restrict__ bat,
                                  u16* __restrict__ o, float* __restrict__ bcat) {
    int i = blockIdx.x * blockDim.x + threadIdx.x;
    if (i < DM * NOA) {
        int k = i / NOA, n = i % NOA;
        float v = (n < 256) ? Woff[k * 256 + n] : Wat[k * 128 + (n - 256)];
        u16 h, l; split1(v, h, l);
        o[(size_t)k * NOA + n] = h;
        o[(size_t)(DM + k) * NOA + n] = h;
        o[(size_t)(2 * DM + k) * NOA + n] = l;
    }
    if (i < NOA) bcat[i] = (i < 256) ? boff[i] : bat[i - 256];
}

// ---------------- mma helpers ----------------
__device__ __forceinline__ void ldsm4(unsigned* r, unsigned addr) {
    asm volatile("ldmatrix.sync.aligned.m8n8.x4.shared.b16 {%0,%1,%2,%3}, [%4];"
                 : "=r"(r[0]), "=r"(r[1]), "=r"(r[2]), "=r"(r[3]) : "r"(addr));
}
__device__ __forceinline__ void ldsm4t(unsigned* r, unsigned addr) {
    asm volatile("ldmatrix.sync.aligned.m8n8.x4.trans.shared.b16 {%0,%1,%2,%3}, [%4];"
                 : "=r"(r[0]), "=r"(r[1]), "=r"(r[2]), "=r"(r[3]) : "r"(addr));
}
__device__ __forceinline__ void mma16816(float* c, const unsigned* a, unsigned b0, unsigned b1) {
    asm volatile("mma.sync.aligned.m16n8k16.row.col.f32.bf16.bf16.f32 "
                 "{%0,%1,%2,%3}, {%4,%5,%6,%7}, {%8,%9}, {%0,%1,%2,%3};"
                 : "+f"(c[0]), "+f"(c[1]), "+f"(c[2]), "+f"(c[3])
                 : "r"(a[0]), "r"(a[1]), "r"(a[2]), "r"(a[3]), "r"(b0), "r"(b1));
}

// ---------------- bf16 GEMM, 3-term (A wraps hi block), cp.async 3-stage ----------------
// A:(M x KA) bf16 pair [hi|lo] row-major; B:(K3 x N) bf16 [hi;hi;lo] row-major; K3 = 1.5*KA.
// Block 64x128x32, 256 threads (8 warps), warp tile 32x32.
// MODE 0: +bias -> f32.  MODE 2: +bias+res -> f32.  MODE 3: relu(+bias) -> bf16 pair (pitch 2N).
#define APITCH 40
#define BPITCH 136
#define ASTG2B (64 * APITCH * 2)
#define BSTG2B (32 * BPITCH * 2)

template<int MODE>
__global__ __launch_bounds__(256, 3)
void hgemm3_kernel(const u16* __restrict__ A, const u16* __restrict__ B,
                   const float* __restrict__ bias, const float* __restrict__ res,
                   float* __restrict__ Cf, u16* __restrict__ Ch,
                   int M, int N, int KA, int K3) {
    __shared__ u16 As[3][64 * APITCH];
    __shared__ u16 Bs[3][32 * BPITCH];

    const int tid  = threadIdx.x;
    const int lane = tid & 31;
    const int wid  = tid >> 5;
    const int wm   = wid >> 2;        // 0..1 (32-row slab)
    const int wn   = wid & 3;         // 0..3 (32-col slab)
    const int bm0  = blockIdx.y * 64;
    const int bn0  = blockIdx.x * 128;

    // loaders: A 64x32 = 256 16B-chunks (1/thread); B 32x128 = 512 chunks (2/thread)
    const int ar  = tid >> 2,  ac8 = (tid & 3) * 8;
    const int br  = tid >> 4,  bc8 = (tid & 15) * 8;
    const u16* gA = A + (size_t)(bm0 + ar) * KA + ac8;
    const u16* gB = B + bn0 + bc8;

    const unsigned smA = (unsigned)__cvta_generic_to_shared(As);
    const unsigned smB = (unsigned)__cvta_generic_to_shared(Bs);
    const unsigned dA  = smA + (ar * APITCH + ac8) * 2;
    const unsigned dB0 = smB + (br * BPITCH + bc8) * 2;
    const unsigned dB1 = smB + ((br + 16) * BPITCH + bc8) * 2;

    const int lrow  = lane & 15;
    const int lcol8 = (lane >> 4) * 8;
    const unsigned fA = smA + ((wm * 32 + lrow) * APITCH + lcol8) * 2;
    const unsigned fB = smB + (lrow * BPITCH + wn * 32 + lcol8) * 2;

    float acc[2][4][4];
#pragma unroll
    for (int mi = 0; mi < 2; mi++)
#pragma unroll
        for (int ni = 0; ni < 4; ni++)
#pragma unroll
            for (int c = 0; c < 4; c++) acc[mi][ni][c] = 0.f;

    const int T = K3 / 32;

#define ISSUE(ST, K0)                                                                \
    {                                                                                \
        int ka_ = (K0) >= KA ? (K0) - KA : (K0);   /* 3rd block reuses A-hi */       \
        asm volatile("cp.async.cg.shared.global [%0], [%1], 16;\n"                   \
                     :: "r"(dA + (ST) * ASTG2B), "l"(gA + ka_));                     \
        asm volatile("cp.async.cg.shared.global [%0], [%1], 16;\n"                   \
                     :: "r"(dB0 + (ST) * BSTG2B), "l"(gB + (size_t)((K0) + br) * N));\
        asm volatile("cp.async.cg.shared.global [%0], [%1], 16;\n"                   \
                     :: "r"(dB1 + (ST) * BSTG2B), "l"(gB + (size_t)((K0) + br + 16) * N)); \
        asm volatile("cp.async.commit_group;\n");                                    \
    }

    ISSUE(0, 0);
    ISSUE(1, 32);

    for (int t = 0; t < T; t++) {
        if (t + 1 < T) { asm volatile("cp.async.wait_group 1;\n" ::: "memory"); }
        else           { asm volatile("cp.async.wait_group 0;\n" ::: "memory"); }
        __syncthreads();
        const int st = t % 3;
        if (t + 2 < T) {
            const int st2 = (t + 2) % 3;
            ISSUE(st2, (t + 2) * 32);
        }
        const unsigned sA = fA + st * ASTG2B;
        const unsigned sB = fB + st * BSTG2B;
#pragma unroll
        for (int kc = 0; kc < 2; kc++) {
            unsigned Af[2][4];
#pragma unroll
            for (int mi = 0; mi < 2; mi++)
                ldsm4(Af[mi], sA + (mi * 16 * APITCH + kc * 16) * 2);
            unsigned Bf[2][4];
#pragma unroll
            for (int nc = 0; nc < 2; nc++)
                ldsm4t(Bf[nc], sB + (kc * 16 * BPITCH + nc * 16) * 2);
#pragma unroll
            for (int mi = 0; mi < 2; mi++)
#pragma unroll
                for (int ni = 0; ni < 4; ni++) {
                    const int nc = ni >> 1, sub = (ni & 1) * 2;
                    mma16816(acc[mi][ni], Af[mi], Bf[nc][sub], Bf[nc][sub + 1]);
                }
        }
        __syncthreads();
    }
#undef ISSUE

    // epilogue
    const int r0 = bm0 + wm * 32 + (lane >> 2);
    const int c0 = bn0 + wn * 32 + (lane & 3) * 2;
#pragma unroll
    for (int mi = 0; mi < 2; mi++) {
#pragma unroll
        for (int ni = 0; ni < 4; ni++) {
            const int col = c0 + ni * 8;
            float2 bb = *(const float2*)&bias[col];
#pragma unroll
            for (int half = 0; half < 2; half++) {
                const int row = r0 + mi * 16 + half * 8;
                float vx = acc[mi][ni][half * 2 + 0] + bb.x;
                float vy = acc[mi][ni][half * 2 + 1] + bb.y;
                if (MODE == 3) {
                    vx = fmaxf(vx, 0.f); vy = fmaxf(vy, 0.f);
                    u16 hx, lx, hy, ly;
                    split1(vx, hx, lx); split1(vy, hy, ly);
                    u16 hp[2] = {hx, hy}, lp[2] = {lx, ly};
                    *(unsigned*)(Ch + (size_t)row * (2 * N) + col)     = *(unsigned*)hp;
                    *(unsigned*)(Ch + (size_t)row * (2 * N) + N + col) = *(unsigned*)lp;
                } else {
                    const size_t off = (size_t)row * N + col;
                    if (MODE == 2) {
                        float2 r = *(const float2*)&res[off];
                        vx += r.x; vy += r.y;
                    }
                    float2 v; v.x = vx; v.y = vy;
                    *(float2*)&Cf[off] = v;
                }
            }
        }
    }
}

// ---------------- deformable sampling (writes bf16 pair) ----------------
__global__ void sample_kernel(const float* __restrict__ value,   // (B*S, 256)
                              const float* __restrict__ offa,    // (ROWS, 384)
                              const float* __restrict__ refp,    // (B, LQ, 4, 2)
                              u16* __restrict__ out2)            // (ROWS, 512) pair
{
    const int gw   = blockIdx.x * (blockDim.x >> 5) + (threadIdx.x >> 5);
    const int lane = threadIdx.x & 31;
    const int h    = gw & 7;
    const int row  = gw >> 3;
    if (row >= ROWS) return;
    const int b = row / LQ;

    const int HH[NLEV]    = {128, 64, 32, 16};
    const int WW[NLEV]    = {128, 64, 32, 16};
    const int START[NLEV] = {0, 16384, 20480, 21504};

    const float* ap = offa + (size_t)row * NOA + 256 + h * 16;
    float lg[16];
#pragma unroll
    for (int j = 0; j < 16; j++) lg[j] = ap[j];
    float mx = lg[0];
#pragma unroll
    for (int j = 1; j < 16; j++) mx = fmaxf(mx, lg[j]);
    float s = 0.f;
#pragma unroll
    for (int j = 0; j < 16; j++) { lg[j] = __expf(lg[j] - mx); s += lg[j]; }
    const float inv = 1.f / s;

    const float* offp = offa + (size_t)row * NOA + h * 32;
    const float* rp   = refp + (size_t)row * (NLEV * 2);

    float acc = 0.f;
#pragma unroll
    for (int l = 0; l < NLEV; l++) {
        const int Hl = HH[l], Wl = WW[l];
        const float rx = rp[l * 2 + 0] * (float)Wl;
        const float ry = rp[l * 2 + 1] * (float)Hl;
        const float* vbase = value + ((size_t)(b * STOT + START[l])) * 256 + h * 32 + lane;
#pragma unroll
        for (int p = 0; p < NPTS; p++) {
            const float x = rx + offp[l * 8 + p * 2 + 0] - 0.5f;
            const float y = ry + offp[l * 8 + p * 2 + 1] - 0.5f;
            const float x0f = floorf(x), y0f = floorf(y);
            const float wx = x - x0f, wy = y - y0f;
            const int x0 = (int)x0f, y0 = (int)y0f;
            const float aw = lg[l * 4 + p] * inv;

            const float w00 = (1.f - wx) * (1.f - wy) * aw;
            const float w10 = wx * (1.f - wy) * aw;
            const float w01 = (1.f - wx) * wy * aw;
            const float w11 = wx * wy * aw;

            if (x0     >= 0 && x0     < Wl && y0     >= 0 && y0     < Hl)
                acc += w00 * vbase[(size_t)(y0 * Wl + x0) * 256];
            if (x0 + 1 >= 0 && x0 + 1 < Wl && y0     >= 0 && y0     < Hl)
                acc += w10 * vbase[(size_t)(y0 * Wl + x0 + 1) * 256];
            if (x0     >= 0 && x0     < Wl && y0 + 1 >= 0 && y0 + 1 < Hl)
                acc += w01 * vbase[(size_t)((y0 + 1) * Wl + x0) * 256];
            if (x0 + 1 >= 0 && x0 + 1 < Wl && y0 + 1 >= 0 && y0 + 1 < Hl)
                acc += w11 * vbase[(size_t)((y0 + 1) * Wl + x0 + 1) * 256];
        }
    }
    u16 hh, ll; split1(acc, hh, ll);
    out2[(size_t)row * 512 + h * 32 + lane]       = hh;
    out2[(size_t)row * 512 + 256 + h * 32 + lane] = ll;
}

// ---------------- layernorm (optionally emits bf16 pair too) ----------------
template<bool PAIR>
__global__ void ln_kernel(const float* __restrict__ in, const float* __restrict__ gam,
                          const float* __restrict__ bet, float* __restrict__ out,
                          u16* __restrict__ out2, int rows) {
    const int warp = (blockIdx.x * blockDim.x + threadIdx.x) >> 5;
    const int lane = threadIdx.x & 31;
    if (warp >= rows) return;
    const float* x = in + (size_t)warp * 256 + lane * 8;
    float4 v0 = *(const float4*)(x);
    float4 v1 = *(const float4*)(x + 4);
    float s  = v0.x + v0.y + v0.z + v0.w + v1.x + v1.y + v1.z + v1.w;
    float ss = v0.x*v0.x + v0.y*v0.y + v0.z*v0.z + v0.w*v0.w
             + v1.x*v1.x + v1.y*v1.y + v1.z*v1.z + v1.w*v1.w;
#pragma unroll
    for (int o = 16; o > 0; o >>= 1) {
        s  += __shfl_xor_sync(0xffffffffu, s,  o);
        ss += __shfl_xor_sync(0xffffffffu, ss, o);
    }
    const float mu  = s * (1.f / 256.f);
    const float var = ss * (1.f / 256.f) - mu * mu;
    const float inv = rsqrtf(var + 1e-5f);

    float4 g0 = *(const float4*)(gam + lane * 8);
    float4 g1 = *(const float4*)(gam + lane * 8 + 4);
    float4 b0 = *(const float4*)(bet + lane * 8);
    float4 b1 = *(const float4*)(bet + lane * 8 + 4);
    float o8[8];
    o8[0] = (v0.x - mu) * inv * g0.x + b0.x;
    o8[1] = (v0.y - mu) * inv * g0.y + b0.y;
    o8[2] = (v0.z - mu) * inv * g0.z + b0.z;
    o8[3] = (v0.w - mu) * inv * g0.w + b0.w;
    o8[4] = (v1.x - mu) * inv * g1.x + b1.x;
    o8[5] = (v1.y - mu) * inv * g1.y + b1.y;
    o8[6] = (v1.z - mu) * inv * g1.z + b1.z;
    o8[7] = (v1.w - mu) * inv * g1.w + b1.w;
    float* y = out + (size_t)warp * 256 + lane * 8;
    *(float4*)(y)     = *(float4*)&o8[0];
    *(float4*)(y + 4) = *(float4*)&o8[4];
    if (PAIR) {
        u16 h[8], l[8];
#pragma unroll
        for (int j = 0; j < 8; j++) split1(o8[j], h[j], l[j]);
        u16* y2 = out2 + (size_t)warp * 512 + lane * 8;
        *(uint2*)(y2)       = *(uint2*)&h[0];
        *(uint2*)(y2 + 4)   = *(uint2*)&h[4];
        *(uint2*)(y2 + 256) = *(uint2*)&l[0];
        *(uint2*)(y2 + 260) = *(uint2*)&l[4];
    }
}

// ---------------- host launcher ----------------
extern "C" void kernel_launch(void* const* d_in, const int* in_sizes, int n_in,
                              void* d_out, int out_size) {
    const float* tgt   = (const float*)d_in[0];
    const float* qpos  = (const float*)d_in[1];
    const float* refp  = (const float*)d_in[2];
    const float* src   = (const float*)d_in[3];
    const float* Wv    = (const float*)d_in[6];
    const float* bv    = (const float*)d_in[7];
    const float* Woff  = (const float*)d_in[8];
    const float* boff  = (const float*)d_in[9];
    const float* Wat   = (const float*)d_in[10];
    const float* bat   = (const float*)d_in[11];
    const float* Wout  = (const float*)d_in[12];
    const float* bout  = (const float*)d_in[13];
    const float* ln1g  = (const float*)d_in[14];
    const float* ln1b  = (const float*)d_in[15];
    const float* W1    = (const float*)d_in[16];
    const float* b1    = (const float*)d_in[17];
    const float* W2    = (const float*)d_in[18];
    const float* b2    = (const float*)d_in[19];
    const float* ln3g  = (const float*)d_in[20];
    const float* ln3b  = (const float*)d_in[21];
    float* out = (float*)d_out;

    u16 *p_q2, *p_src2, *p_smp2, *p_x2, *p_h2, *p_wv2, *p_wcat2, *p_wout2, *p_w12, *p_w22;
    float *p_val, *p_offa, *p_xpre, *p_x, *p_res, *p_bcat;
    cudaGetSymbolAddress((void**)&p_q2,    g_q2);
    cudaGetSymbolAddress((void**)&p_src2,  g_src2);
    cudaGetSymbolAddress((void**)&p_val,   g_val);
    cudaGetSymbolAddress((void**)&p_offa,  g_offa);
    cudaGetSymbolAddress((void**)&p_smp2,  g_smp2);
    cudaGetSymbolAddress((void**)&p_xpre,  g_xpre);
    cudaGetSymbolAddress((void**)&p_x,     g_x);
    cudaGetSymbolAddress((void**)&p_x2,    g_x2);
    cudaGetSymbolAddress((void**)&p_h2,    g_h2);
    cudaGetSymbolAddress((void**)&p_res,   g_res);
    cudaGetSymbolAddress((void**)&p_wv2,   g_wv2);
    cudaGetSymbolAddress((void**)&p_wcat2, g_wcat2);
    cudaGetSymbolAddress((void**)&p_wout2, g_wout2);
    cudaGetSymbolAddress((void**)&p_w12,   g_w12);
    cudaGetSymbolAddress((void**)&p_w22,   g_w22);
    cudaGetSymbolAddress((void**)&p_bcat,  g_bcat);

    // prep: weights -> 3-block bf16 [hi; hi; lo]
    wcvt_kernel<<<(DM * DM + 255) / 256, 256>>>(Wv, p_wv2, DM, DM);
    wcvt_kernel<<<(DM * DM + 255) / 256, 256>>>(Wout, p_wout2, DM, DM);
    wcvt_kernel<<<(DM * DFFN + 255) / 256, 256>>>(W1, p_w12, DM, DFFN);
    wcvt_kernel<<<(DFFN * DM + 255) / 256, 256>>>(W2, p_w22, DFFN, DM);
    concat_cvt_kernel<<<(DM * NOA + 255) / 256, 256>>>(Woff, Wat, boff, bat, p_wcat2, p_bcat);

    // activations -> pairs
    add_cvt_kernel<<<(ROWS * 64 + 255) / 256, 256>>>(tgt, qpos, p_q2);
    cvt_kernel<<<(MVAL * 64 + 255) / 256, 256>>>(src, p_src2, MVAL);

    // value = src @ Wv + bv          (3-term: KA=512, K3=768)
    hgemm3_kernel<0><<<dim3(DM / 128, MVAL / 64), 256>>>(p_src2, p_wv2, bv, nullptr,
                                                         p_val, nullptr, MVAL, DM, 512, 768);
    // offa = q @ Wcat + bcat
    hgemm3_kernel<0><<<dim3(NOA / 128, ROWS / 64), 256>>>(p_q2, p_wcat2, p_bcat, nullptr,
                                                          p_offa, nullptr, ROWS, NOA, 512, 768);
    // sampling -> smp pair
    sample_kernel<<<(ROWS * NHEADS) / 8, 256>>>(p_val, p_offa, refp, p_smp2);
    // x_pre = smp @ Wout + bout + tgt
    hgemm3_kernel<2><<<dim3(DM / 128, ROWS / 64), 256>>>(p_smp2, p_wout2, bout, tgt,
                                                         p_xpre, nullptr, ROWS, DM, 512, 768);
    // x = LN1(x_pre)  (f32 + pair)
    ln_kernel<true><<<ROWS / 8, 256>>>(p_xpre, ln1g, ln1b, p_x, p_x2, ROWS);
    // h = relu(x @ W1 + b1) -> pair only
    hgemm3_kernel<3><<<dim3(DFFN / 128, ROWS / 64), 256>>>(p_x2, p_w12, b1, nullptr,
                                                           nullptr, p_h2, ROWS, DFFN, 512, 768);
    // y_pre = h @ W2 + b2 + x        (KA=2048, K3=3072)
    hgemm3_kernel<2><<<dim3(DM / 128, ROWS / 64), 256>>>(p_h2, p_w22, b2, p_x,
                                                         p_res, nullptr, ROWS, DM, 2048, 3072);
    // out = LN3(y_pre)
    ln_kernel<false><<<ROWS / 8, 256>>>(p_res, ln3g, ln3b, out, nullptr, ROWS);
}

// round 15
// speedup vs baseline: 1.2564x; 1.2564x over previous
#include <cuda_runtime.h>
#include <cuda_fp16.h>
#include <math.h>

// ---------------- problem constants ----------------
#define BATCH    2
#define LQ       8192
#define DM       256
#define DFFN     1024
#define NHEADS   8
#define NLEV     4
#define NPTS     4
#define STOT     21760           // 128*128 + 64*64 + 32*32 + 16*16
#define ROWS     (BATCH*LQ)      // 16384
#define MVAL     (BATCH*STOT)    // 43520
#define NOA      384             // fused off(256)+attn(128)

typedef unsigned short u16;

// ---------------- device scratch (allocation-free) ----------------
__device__ u16   g_q2  [ROWS * 512];        // (tgt+pos) hi|lo fp16 pairs
__device__ u16   g_src2[MVAL * 512];
__device__ float g_val [MVAL * DM];
__device__ float g_offa[ROWS * NOA];
__device__ u16   g_smp2[ROWS * 512];
__device__ float g_xpre[ROWS * DM];
__device__ float g_x   [ROWS * DM];
__device__ u16   g_x2  [ROWS * 512];
__device__ u16   g_h2  [ROWS * 2048];
__device__ float g_res [ROWS * DM];
__device__ u16   g_wv2  [512 * DM];
__device__ u16   g_wcat2[512 * NOA];
__device__ u16   g_wout2[512 * DM];
__device__ u16   g_w12  [512 * DFFN];
__device__ u16   g_w22  [2048 * DM];
__device__ float g_bcat [NOA];

// ---------------- fp16 hi/lo helpers ----------------
__device__ __forceinline__ void split1(float v, u16& h, u16& l) {
    __half hb = __float2half_rn(v);
    __half lb = __float2half_rn(v - __half2float(hb));
    h = *(u16*)&hb; l = *(u16*)&lb;
}

// q2 = pair(tgt + qpos); rows x 512 (cols 0..255 hi, 256..511 lo)
__global__ void add_cvt_kernel(const float* __restrict__ a, const float* __restrict__ b,
                               u16* __restrict__ o) {
    int i = blockIdx.x * blockDim.x + threadIdx.x;       // ROWS*64
    if (i >= ROWS * 64) return;
    int row = i >> 6, c = (i & 63) * 4;
    float4 x = ((const float4*)(a + (size_t)row * 256))[c >> 2];
    float4 y = ((const float4*)(b + (size_t)row * 256))[c >> 2];
    x.x += y.x; x.y += y.y; x.z += y.z; x.w += y.w;
    u16 h[4], l[4];
    split1(x.x, h[0], l[0]); split1(x.y, h[1], l[1]);
    split1(x.z, h[2], l[2]); split1(x.w, h[3], l[3]);
    *(uint2*)(o + (size_t)row * 512 + c)       = *(uint2*)h;
    *(uint2*)(o + (size_t)row * 512 + 256 + c) = *(uint2*)l;
}

// pair-convert activations: (rows x 256) f32 -> (rows x 512) u16
__global__ void cvt_kernel(const float* __restrict__ a, u16* __restrict__ o, int rows) {
    int i = blockIdx.x * blockDim.x + threadIdx.x;
    if (i >= rows * 64) return;
    int row = i >> 6, c = (i & 63) * 4;
    float4 x = ((const float4*)(a + (size_t)row * 256))[c >> 2];
    u16 h[4], l[4];
    split1(x.x, h[0], l[0]); split1(x.y, h[1], l[1]);
    split1(x.z, h[2], l[2]); split1(x.w, h[3], l[3]);
    *(uint2*)(o + (size_t)row * 512 + c)       = *(uint2*)h;
    *(uint2*)(o + (size_t)row * 512 + 256 + c) = *(uint2*)l;
}

// weight convert: (K x N) f32 -> (2K x N) u16 (hi rows then lo rows)
__global__ void wcvt_kernel(const float* __restrict__ w, u16* __restrict__ o, int K, int N) {
    int i = blockIdx.x * blockDim.x + threadIdx.x;
    if (i >= K * N) return;
    int k = i / N, n = i % N;
    u16 h, l; split1(w[i], h, l);
    o[(size_t)k * N + n] = h;
    o[(size_t)(K + k) * N + n] = l;
}

// concat Woff|Wat -> pair (512 x 384) + bias concat
__global__ void concat_cvt_kernel(const float* __restrict__ Woff, const float* __restrict__ Wat,
                                  const float* __restrict__ boff, const float* __restrict__ bat,
                                  u16* __restrict__ o, float* __restrict__ bcat) {
    int i = blockIdx.x * blockDim.x + threadIdx.x;
    if (i < DM * NOA) {
        int k = i / NOA, n = i % NOA;
        float v = (n < 256) ? Woff[k * 256 + n] : Wat[k * 128 + (n - 256)];
        u16 h, l; split1(v, h, l);
        o[(size_t)k * NOA + n] = h;
        o[(size_t)(DM + k) * NOA + n] = l;
    }
    if (i < NOA) bcat[i] = (i < 256) ? boff[i] : bat[i - 256];
}

// ---------------- mma helpers (fp16 inputs, fp32 accum) ----------------
__device__ __forceinline__ void ldsm4(unsigned* r, unsigned addr) {
    asm volatile("ldmatrix.sync.aligned.m8n8.x4.shared.b16 {%0,%1,%2,%3}, [%4];"
                 : "=r"(r[0]), "=r"(r[1]), "=r"(r[2]), "=r"(r[3]) : "r"(addr));
}
__device__ __forceinline__ void ldsm4t(unsigned* r, unsigned addr) {
    asm volatile("ldmatrix.sync.aligned.m8n8.x4.trans.shared.b16 {%0,%1,%2,%3}, [%4];"
                 : "=r"(r[0]), "=r"(r[1]), "=r"(r[2]), "=r"(r[3]) : "r"(addr));
}
__device__ __forceinline__ void mma16816(float* c, const unsigned* a, unsigned b0, unsigned b1) {
    asm volatile("mma.sync.aligned.m16n8k16.row.col.f32.f16.f16.f32 "
                 "{%0,%1,%2,%3}, {%4,%5,%6,%7}, {%8,%9}, {%0,%1,%2,%3};"
                 : "+f"(c[0]), "+f"(c[1]), "+f"(c[2]), "+f"(c[3])
                 : "r"(a[0]), "r"(a[1]), "r"(a[2]), "r"(a[3]), "r"(b0), "r"(b1));
}

// ---------------- fp16 GEMM, cp.async 3-stage ----------------
// C = op(A2@B2 + bias [...]); A2:(M x K2) fp16 row-major, B2:(K2 x N) fp16 row-major.
// Block 128x128x32, 256 threads, warp tile 64x32.
// MODE 0: +bias -> f32.  MODE 2: +bias+res -> f32.  MODE 3: relu(+bias) -> fp16 pair (pitch 2N).
#define APITCH 40
#define BPITCH 136
#define ASTG2B (128 * APITCH * 2)
#define BSTG2B (32 * BPITCH * 2)

template<int MODE>
__global__ __launch_bounds__(256, 2)
void hgemm2_kernel(const u16* __restrict__ A, const u16* __restrict__ B,
                   const float* __restrict__ bias, const float* __restrict__ res,
                   float* __restrict__ Cf, u16* __restrict__ Ch,
                   int M, int N, int K2) {
    __shared__ u16 As[3][128 * APITCH];
    __shared__ u16 Bs[3][32 * BPITCH];

    const int tid  = threadIdx.x;
    const int lane = tid & 31;
    const int wid  = tid >> 5;
    const int wm   = wid >> 2;        // 0..1
    const int wn   = wid & 3;         // 0..3
    const int bm0  = blockIdx.y * 128;
    const int bn0  = blockIdx.x * 128;

    // loaders: A 128x32 (4 chunks/row), B 32x128 (16 chunks/row); 2 chunks each per thread
    const int ar  = tid >> 2,  ac8 = (tid & 3) * 8;
    const int br  = tid >> 4,  bc8 = (tid & 15) * 8;
    const u16* gA0 = A + (size_t)(bm0 + ar) * K2 + ac8;
    const u16* gA1 = A + (size_t)(bm0 + ar + 64) * K2 + ac8;
    const u16* gB  = B + bn0 + bc8;

    const unsigned smA = (unsigned)__cvta_generic_to_shared(As);
    const unsigned smB = (unsigned)__cvta_generic_to_shared(Bs);
    const unsigned dA0 = smA + (ar * APITCH + ac8) * 2;
    const unsigned dA1 = smA + ((ar + 64) * APITCH + ac8) * 2;
    const unsigned dB0 = smB + (br * BPITCH + bc8) * 2;
    const unsigned dB1 = smB + ((br + 16) * BPITCH + bc8) * 2;

    const int lrow  = lane & 15;
    const int lcol8 = (lane >> 4) * 8;
    const unsigned fA = smA + ((wm * 64 + lrow) * APITCH + lcol8) * 2;
    const unsigned fB = smB + (lrow * BPITCH + wn * 32 + lcol8) * 2;

    float acc[4][4][4];
#pragma unroll
    for (int mi = 0; mi < 4; mi++)
#pragma unroll
        for (int ni = 0; ni < 4; ni++)
#pragma unroll
            for (int c = 0; c < 4; c++) acc[mi][ni][c] = 0.f;

    const int T = K2 / 32;

#define ISSUE(ST, K0)                                                                \
    {                                                                                \
        asm volatile("cp.async.cg.shared.global [%0], [%1], 16;\n"                   \
                     :: "r"(dA0 + (ST) * ASTG2B), "l"(gA0 + (K0)));                  \
        asm volatile("cp.async.cg.shared.global [%0], [%1], 16;\n"                   \
                     :: "r"(dA1 + (ST) * ASTG2B), "l"(gA1 + (K0)));                  \
        asm volatile("cp.async.cg.shared.global [%0], [%1], 16;\n"                   \
                     :: "r"(dB0 + (ST) * BSTG2B), "l"(gB + (size_t)((K0) + br) * N));\
        asm volatile("cp.async.cg.shared.global [%0], [%1], 16;\n"                   \
                     :: "r"(dB1 + (ST) * BSTG2B), "l"(gB + (size_t)((K0) + br + 16) * N)); \
        asm volatile("cp.async.commit_group;\n");                                    \
    }

    ISSUE(0, 0);
    ISSUE(1, 32);

    for (int t = 0; t < T; t++) {
        if (t + 1 < T) { asm volatile("cp.async.wait_group 1;\n" ::: "memory"); }
        else           { asm volatile("cp.async.wait_group 0;\n" ::: "memory"); }
        __syncthreads();
        const int st = t % 3;
        if (t + 2 < T) {
            const int st2 = (t + 2) % 3;
            ISSUE(st2, (t + 2) * 32);
        }
        const unsigned sA = fA + st * ASTG2B;
        const unsigned sB = fB + st * BSTG2B;
#pragma unroll
        for (int kc = 0; kc < 2; kc++) {
            unsigned Af[4][4];
#pragma unroll
            for (int mi = 0; mi < 4; mi++)
                ldsm4(Af[mi], sA + (mi * 16 * APITCH + kc * 16) * 2);
            unsigned Bf[2][4];
#pragma unroll
            for (int nc = 0; nc < 2; nc++)
                ldsm4t(Bf[nc], sB + (kc * 16 * BPITCH + nc * 16) * 2);
#pragma unroll
            for (int mi = 0; mi < 4; mi++)
#pragma unroll
                for (int ni = 0; ni < 4; ni++) {
                    const int nc = ni >> 1, sub = (ni & 1) * 2;
                    mma16816(acc[mi][ni], Af[mi], Bf[nc][sub], Bf[nc][sub + 1]);
                }
        }
        __syncthreads();
    }
#undef ISSUE

    // epilogue
    const int r0 = bm0 + wm * 64 + (lane >> 2);
    const int c0 = bn0 + wn * 32 + (lane & 3) * 2;
#pragma unroll
    for (int mi = 0; mi < 4; mi++) {
#pragma unroll
        for (int ni = 0; ni < 4; ni++) {
            const int col = c0 + ni * 8;
            float2 bb = *(const float2*)&bias[col];
#pragma unroll
            for (int half = 0; half < 2; half++) {
                const int row = r0 + mi * 16 + half * 8;
                float vx = acc[mi][ni][half * 2 + 0] + bb.x;
                float vy = acc[mi][ni][half * 2 + 1] + bb.y;
                if (MODE == 3) {
                    vx = fmaxf(vx, 0.f); vy = fmaxf(vy, 0.f);
                    u16 hx, lx, hy, ly;
                    split1(vx, hx, lx); split1(vy, hy, ly);
                    u16 hp[2] = {hx, hy}, lp[2] = {lx, ly};
                    *(unsigned*)(Ch + (size_t)row * (2 * N) + col)     = *(unsigned*)hp;
                    *(unsigned*)(Ch + (size_t)row * (2 * N) + N + col) = *(unsigned*)lp;
                } else {
                    const size_t off = (size_t)row * N + col;
                    if (MODE == 2) {
                        float2 r = *(const float2*)&res[off];
                        vx += r.x; vy += r.y;
                    }
                    float2 v; v.x = vx; v.y = vy;
                    *(float2*)&Cf[off] = v;
                }
            }
        }
    }
}

// ---------------- deformable sampling (writes fp16 pair) ----------------
__global__ void sample_kernel(const float* __restrict__ value,   // (B*S, 256)
                              const float* __restrict__ offa,    // (ROWS, 384)
                              const float* __restrict__ refp,    // (B, LQ, 4, 2)
                              u16* __restrict__ out2)            // (ROWS, 512) pair
{
    const int gw   = blockIdx.x * (blockDim.x >> 5) + (threadIdx.x >> 5);
    const int lane = threadIdx.x & 31;
    const int h    = gw & 7;
    const int row  = gw >> 3;
    if (row >= ROWS) return;
    const int b = row / LQ;

    const int HH[NLEV]    = {128, 64, 32, 16};
    const int WW[NLEV]    = {128, 64, 32, 16};
    const int START[NLEV] = {0, 16384, 20480, 21504};

    const float* ap = offa + (size_t)row * NOA + 256 + h * 16;
    float lg[16];
#pragma unroll
    for (int j = 0; j < 16; j++) lg[j] = ap[j];
    float mx = lg[0];
#pragma unroll
    for (int j = 1; j < 16; j++) mx = fmaxf(mx, lg[j]);
    float s = 0.f;
#pragma unroll
    for (int j = 0; j < 16; j++) { lg[j] = __expf(lg[j] - mx); s += lg[j]; }
    const float inv = 1.f / s;

    const float* offp = offa + (size_t)row * NOA + h * 32;
    const float* rp   = refp + (size_t)row * (NLEV * 2);

    float acc = 0.f;
#pragma unroll
    for (int l = 0; l < NLEV; l++) {
        const int Hl = HH[l], Wl = WW[l];
        const float rx = rp[l * 2 + 0] * (float)Wl;
        const float ry = rp[l * 2 + 1] * (float)Hl;
        const float* vbase = value + ((size_t)(b * STOT + START[l])) * 256 + h * 32 + lane;
#pragma unroll
        for (int p = 0; p < NPTS; p++) {
            const float x = rx + offp[l * 8 + p * 2 + 0] - 0.5f;
            const float y = ry + offp[l * 8 + p * 2 + 1] - 0.5f;
            const float x0f = floorf(x), y0f = floorf(y);
            const float wx = x - x0f, wy = y - y0f;
            const int x0 = (int)x0f, y0 = (int)y0f;
            const float aw = lg[l * 4 + p] * inv;

            const float w00 = (1.f - wx) * (1.f - wy) * aw;
            const float w10 = wx * (1.f - wy) * aw;
            const float w01 = (1.f - wx) * wy * aw;
            const float w11 = wx * wy * aw;

            if (x0     >= 0 && x0     < Wl && y0     >= 0 && y0     < Hl)
                acc += w00 * vbase[(size_t)(y0 * Wl + x0) * 256];
            if (x0 + 1 >= 0 && x0 + 1 < Wl && y0     >= 0 && y0     < Hl)
                acc += w10 * vbase[(size_t)(y0 * Wl + x0 + 1) * 256];
            if (x0     >= 0 && x0     < Wl && y0 + 1 >= 0 && y0 + 1 < Hl)
                acc += w01 * vbase[(size_t)((y0 + 1) * Wl + x0) * 256];
            if (x0 + 1 >= 0 && x0 + 1 < Wl && y0 + 1 >= 0 && y0 + 1 < Hl)
                acc += w11 * vbase[(size_t)((y0 + 1) * Wl + x0 + 1) * 256];
        }
    }
    u16 hh, ll; split1(acc, hh, ll);
    out2[(size_t)row * 512 + h * 32 + lane]       = hh;
    out2[(size_t)row * 512 + 256 + h * 32 + lane] = ll;
}

// ---------------- layernorm (optionally emits fp16 pair too) ----------------
template<bool PAIR>
__global__ void ln_kernel(const float* __restrict__ in, const float* __restrict__ gam,
                          const float* __restrict__ bet, float* __restrict__ out,
                          u16* __restrict__ out2, int rows) {
    const int warp = (blockIdx.x * blockDim.x + threadIdx.x) >> 5;
    const int lane = threadIdx.x & 31;
    if (warp >= rows) return;
    const float* x = in + (size_t)warp * 256 + lane * 8;
    float4 v0 = *(const float4*)(x);
    float4 v1 = *(const float4*)(x + 4);
    float s  = v0.x + v0.y + v0.z + v0.w + v1.x + v1.y + v1.z + v1.w;
    float ss = v0.x*v0.x + v0.y*v0.y + v0.z*v0.z + v0.w*v0.w
             + v1.x*v1.x + v1.y*v1.y + v1.z*v1.z + v1.w*v1.w;
#pragma unroll
    for (int o = 16; o > 0; o >>= 1) {
        s  += __shfl_xor_sync(0xffffffffu, s,  o);
        ss += __shfl_xor_sync(0xffffffffu, ss, o);
    }
    const float mu  = s * (1.f / 256.f);
    const float var = ss * (1.f / 256.f) - mu * mu;
    const float inv = rsqrtf(var + 1e-5f);

    float4 g0 = *(const float4*)(gam + lane * 8);
    float4 g1 = *(const float4*)(gam + lane * 8 + 4);
    float4 b0 = *(const float4*)(bet + lane * 8);
    float4 b1 = *(const float4*)(bet + lane * 8 + 4);
    float o8[8];
    o8[0] = (v0.x - mu) * inv * g0.x + b0.x;
    o8[1] = (v0.y - mu) * inv * g0.y + b0.y;
    o8[2] = (v0.z - mu) * inv * g0.z + b0.z;
    o8[3] = (v0.w - mu) * inv * g0.w + b0.w;
    o8[4] = (v1.x - mu) * inv * g1.x + b1.x;
    o8[5] = (v1.y - mu) * inv * g1.y + b1.y;
    o8[6] = (v1.z - mu) * inv * g1.z + b1.z;
    o8[7] = (v1.w - mu) * inv * g1.w + b1.w;
    float* y = out + (size_t)warp * 256 + lane * 8;
    *(float4*)(y)     = *(float4*)&o8[0];
    *(float4*)(y + 4) = *(float4*)&o8[4];
    if (PAIR) {
        u16 h[8], l[8];
#pragma unroll
        for (int j = 0; j < 8; j++) split1(o8[j], h[j], l[j]);
        u16* y2 = out2 + (size_t)warp * 512 + lane * 8;
        *(uint2*)(y2)       = *(uint2*)&h[0];
        *(uint2*)(y2 + 4)   = *(uint2*)&h[4];
        *(uint2*)(y2 + 256) = *(uint2*)&l[0];
        *(uint2*)(y2 + 260) = *(uint2*)&l[4];
    }
}

// ---------------- host launcher ----------------
extern "C" void kernel_launch(void* const* d_in, const int* in_sizes, int n_in,
                              void* d_out, int out_size) {
    const float* tgt   = (const float*)d_in[0];
    const float* qpos  = (const float*)d_in[1];
    const float* refp  = (const float*)d_in[2];
    const float* src   = (const float*)d_in[3];
    const float* Wv    = (const float*)d_in[6];
    const float* bv    = (const float*)d_in[7];
    const float* Woff  = (const float*)d_in[8];
    const float* boff  = (const float*)d_in[9];
    const float* Wat   = (const float*)d_in[10];
    const float* bat   = (const float*)d_in[11];
    const float* Wout  = (const float*)d_in[12];
    const float* bout  = (const float*)d_in[13];
    const float* ln1g  = (const float*)d_in[14];
    const float* ln1b  = (const float*)d_in[15];
    const float* W1    = (const float*)d_in[16];
    const float* b1    = (const float*)d_in[17];
    const float* W2    = (const float*)d_in[18];
    const float* b2    = (const float*)d_in[19];
    const float* ln3g  = (const float*)d_in[20];
    const float* ln3b  = (const float*)d_in[21];
    float* out = (float*)d_out;

    u16 *p_q2, *p_src2, *p_smp2, *p_x2, *p_h2, *p_wv2, *p_wcat2, *p_wout2, *p_w12, *p_w22;
    float *p_val, *p_offa, *p_xpre, *p_x, *p_res, *p_bcat;
    cudaGetSymbolAddress((void**)&p_q2,    g_q2);
    cudaGetSymbolAddress((void**)&p_src2,  g_src2);
    cudaGetSymbolAddress((void**)&p_val,   g_val);
    cudaGetSymbolAddress((void**)&p_offa,  g_offa);
    cudaGetSymbolAddress((void**)&p_smp2,  g_smp2);
    cudaGetSymbolAddress((void**)&p_xpre,  g_xpre);
    cudaGetSymbolAddress((void**)&p_x,     g_x);
    cudaGetSymbolAddress((void**)&p_x2,    g_x2);
    cudaGetSymbolAddress((void**)&p_h2,    g_h2);
    cudaGetSymbolAddress((void**)&p_res,   g_res);
    cudaGetSymbolAddress((void**)&p_wv2,   g_wv2);
    cudaGetSymbolAddress((void**)&p_wcat2, g_wcat2);
    cudaGetSymbolAddress((void**)&p_wout2, g_wout2);
    cudaGetSymbolAddress((void**)&p_w12,   g_w12);
    cudaGetSymbolAddress((void**)&p_w22,   g_w22);
    cudaGetSymbolAddress((void**)&p_bcat,  g_bcat);

    // prep: weights -> fp16 pairs
    wcvt_kernel<<<(DM * DM + 255) / 256, 256>>>(Wv, p_wv2, DM, DM);
    wcvt_kernel<<<(DM * DM + 255) / 256, 256>>>(Wout, p_wout2, DM, DM);
    wcvt_kernel<<<(DM * DFFN + 255) / 256, 256>>>(W1, p_w12, DM, DFFN);
    wcvt_kernel<<<(DFFN * DM + 255) / 256, 256>>>(W2, p_w22, DFFN, DM);
    concat_cvt_kernel<<<(DM * NOA + 255) / 256, 256>>>(Woff, Wat, boff, bat, p_wcat2, p_bcat);

    // activations -> pairs
    add_cvt_kernel<<<(ROWS * 64 + 255) / 256, 256>>>(tgt, qpos, p_q2);
    cvt_kernel<<<(MVAL * 64 + 255) / 256, 256>>>(src, p_src2, MVAL);

    // value = src @ Wv + bv
    hgemm2_kernel<0><<<dim3(DM / 128, MVAL / 128), 256>>>(p_src2, p_wv2, bv, nullptr,
                                                          p_val, nullptr, MVAL, DM, 512);
    // offa = q @ Wcat + bcat
    hgemm2_kernel<0><<<dim3(NOA / 128, ROWS / 128), 256>>>(p_q2, p_wcat2, p_bcat, nullptr,
                                                           p_offa, nullptr, ROWS, NOA, 512);
    // sampling -> smp pair
    sample_kernel<<<(ROWS * NHEADS) / 8, 256>>>(p_val, p_offa, refp, p_smp2);
    // x_pre = smp @ Wout + bout + tgt
    hgemm2_kernel<2><<<dim3(DM / 128, ROWS / 128), 256>>>(p_smp2, p_wout2, bout, tgt,
                                                          p_xpre, nullptr, ROWS, DM, 512);
    // x = LN1(x_pre)  (f32 + pair)
    ln_kernel<true><<<ROWS / 8, 256>>>(p_xpre, ln1g, ln1b, p_x, p_x2, ROWS);
    // h = relu(x @ W1 + b1) -> pair only
    hgemm2_kernel<3><<<dim3(DFFN / 128, ROWS / 128), 256>>>(p_x2, p_w12, b1, nullptr,
                                                            nullptr, p_h2, ROWS, DFFN, 512);
    // y_pre = h @ W2 + b2 + x
    hgemm2_kernel<2><<<dim3(DM / 128, ROWS / 128), 256>>>(p_h2, p_w22, b2, p_x,
                                                          p_res, nullptr, ROWS, DM, 2048);
    // out = LN3(y_pre)
    ln_kernel<false><<<ROWS / 8, 256>>>(p_res, ln3g, ln3b, out, nullptr, ROWS);
}